// round 14
// baseline (speedup 1.0000x reference)
#include <cuda_runtime.h>
#include <math.h>
#include <stdint.h>

#define HW  4096
#define CH  256
#define NB  4

// Stage-1 outputs (all bf16)
__device__ uint16_t g_qT[(size_t)NB * HW * 128];   // q: [n][hw][c]
__device__ uint16_t g_kT[(size_t)NB * HW * 128];   // k: [n][hw][c]
__device__ uint16_t g_vb[(size_t)NB * 256 * HW];   // v: [n][c][hw]

// ---------------------------------------------------------------------------
__device__ __forceinline__ uint32_t pack_bf16(float lo, float hi) {
    uint32_t r;
    asm("cvt.rn.bf16x2.f32 %0, %1, %2;" : "=r"(r) : "f"(hi), "f"(lo));
    return r;
}
__device__ __forceinline__ uint16_t bf16_bits(float x) {
    uint16_t r;
    asm("cvt.rn.bf16.f32 %0, %1;" : "=h"(r) : "f"(x));
    return r;
}

__device__ __forceinline__ void mma_u(float* d, const uint32_t* a, uint32_t b0, uint32_t b1) {
    asm volatile(
        "mma.sync.aligned.m16n8k8.row.col.f32.tf32.tf32.f32 "
        "{%0,%1,%2,%3},{%4,%5,%6,%7},{%8,%9},{%0,%1,%2,%3};\n"
        : "+f"(d[0]), "+f"(d[1]), "+f"(d[2]), "+f"(d[3])
        : "r"(a[0]), "r"(a[1]), "r"(a[2]), "r"(a[3]), "r"(b0), "r"(b1));
}

__device__ __forceinline__ void mma_bf16(float* d, const uint32_t* a, uint32_t b0, uint32_t b1) {
    asm volatile(
        "mma.sync.aligned.m16n8k16.row.col.f32.bf16.bf16.f32 "
        "{%0,%1,%2,%3},{%4,%5,%6,%7},{%8,%9},{%0,%1,%2,%3};\n"
        : "+f"(d[0]), "+f"(d[1]), "+f"(d[2]), "+f"(d[3])
        : "r"(a[0]), "r"(a[1]), "r"(a[2]), "r"(a[3]), "r"(b0), "r"(b1));
}

__device__ __forceinline__ void ldsm_x4(uint32_t* r, uint32_t saddr) {
    asm volatile("ldmatrix.sync.aligned.m8n8.x4.shared.b16 {%0,%1,%2,%3}, [%4];"
                 : "=r"(r[0]), "=r"(r[1]), "=r"(r[2]), "=r"(r[3]) : "r"(saddr));
}

__device__ __forceinline__ void st_shared_b32(uint32_t saddr, uint32_t v) {
    asm volatile("st.shared.b32 [%0], %1;" :: "r"(saddr), "r"(v));
}

__device__ __forceinline__ void cp_async16(uint32_t saddr, const void* gptr) {
    asm volatile("cp.async.ca.shared.global [%0], [%1], 16;\n" :: "r"(saddr), "l"(gptr));
}
__device__ __forceinline__ void cp_commit() {
    asm volatile("cp.async.commit_group;\n" ::: "memory");
}
__device__ __forceinline__ void cp_wait0() {
    asm volatile("cp.async.wait_group 0;\n" ::: "memory");
}

// Fast e^x on the FMA pipe
__device__ __forceinline__ float fexp(float x) {
    float y = fmaxf(x * 1.4426950408889634f, -126.0f);
    float n = rintf(y);
    float f = y - n;
    float p = 1.3333558e-3f;
    p = p * f + 9.6181291e-3f;
    p = p * f + 5.5504109e-2f;
    p = p * f + 2.4022650e-1f;
    p = p * f + 6.9314718e-1f;
    p = p * f + 1.0f;
    return p * __int_as_float(((int)n + 127) << 23);
}

// ---------------------------------------------------------------------------
// Stage 1: x-resident, ldsm + tf32 mma, W fills via cp.async. (unchanged)
// ---------------------------------------------------------------------------
#define S1_ST 260
#define S1_OFF_W (128 * S1_ST)
#define S1_SMEM ((128 + 64) * S1_ST * 4)

__global__ void __launch_bounds__(256) stage1_kernel(
    const float* __restrict__ x,
    const float* __restrict__ w1, const float* __restrict__ b1, const float* __restrict__ a1,
    const float* __restrict__ w2, const float* __restrict__ b2, const float* __restrict__ a2,
    const float* __restrict__ wa, const float* __restrict__ ba, const float* __restrict__ aa)
{
    extern __shared__ float sm[];
    float* XsT = sm;
    const uint32_t sbase = (uint32_t)__cvta_generic_to_shared(sm);

    const int hbase = blockIdx.x * 128;
    const int n     = blockIdx.y;
    const int tid   = threadIdx.x;
    const int w = tid >> 5, lane = tid & 31, grp = lane >> 2, qd = lane & 3;

    const float* xb = x + (size_t)n * CH * HW;

    for (int idx = tid; idx < 256 * 128; idx += 256) {
        int c = idx >> 7, hh = idx & 127;
        XsT[hh * S1_ST + c] = xb[(size_t)c * HW + hbase + hh];
    }

    const int rpA = (lane & 7) + (lane & 8);
    const int kcA = (lane >> 4) * 16;
    const int rpB = lane & 7;
    const int cbB = (lane >> 3) * 16;

    const int mo = (w & 1) * 32;
    const int nh = (w >> 1) * 32;

    const uint32_t wa_base = sbase + (uint32_t)((S1_OFF_W + (mo + rpA) * S1_ST) * 4 + kcA);
    const uint32_t xb_base = sbase + (uint32_t)(((nh + rpB) * S1_ST) * 4 + cbB);

    uint16_t* gqT = g_qT + (size_t)n * HW * 128;
    uint16_t* gkT = g_kT + (size_t)n * HW * 128;
    uint16_t* gvb = g_vb + (size_t)n * 256 * HW;

    for (int ob = 0; ob < 8; ++ob) {
        const int obase = ob * 64;
        __syncthreads();
        #pragma unroll 4
        for (int r = 0; r < 16; ++r) {
            int idx = tid + r * 256;
            int oo = idx >> 6, ch = idx & 63;
            int o = obase + oo;
            const float* wp = (o < 128) ? w1 + (size_t)o * CH
                            : (o < 256) ? w2 + (size_t)(o - 128) * CH
                                        : wa + (size_t)(o - 256) * CH;
            cp_async16(sbase + (uint32_t)((S1_OFF_W + oo * S1_ST) * 4 + ch * 16),
                       wp + ch * 4);
        }
        cp_commit(); cp_wait0();
        __syncthreads();

        float acc[2][4][4] = {};
        #pragma unroll 4
        for (int sp = 0; sp < 16; ++sp) {
            uint32_t av[2][2][4];
            #pragma unroll
            for (int mi = 0; mi < 2; ++mi) {
                ldsm_x4(av[mi][0], wa_base + (uint32_t)(mi * 16 * S1_ST * 4 + sp * 64));
                ldsm_x4(av[mi][1], wa_base + (uint32_t)(mi * 16 * S1_ST * 4 + sp * 64 + 32));
            }
            #pragma unroll
            for (int nj = 0; nj < 4; ++nj) {
                uint32_t bq[4];
                ldsm_x4(bq, xb_base + (uint32_t)(nj * 8 * S1_ST * 4 + sp * 64));
                #pragma unroll
                for (int mi = 0; mi < 2; ++mi) {
                    mma_u(acc[mi][nj], av[mi][0], bq[0], bq[1]);
                    mma_u(acc[mi][nj], av[mi][1], bq[2], bq[3]);
                }
            }
        }

        #pragma unroll
        for (int mi = 0; mi < 2; ++mi) {
            int o0 = obase + mo + mi * 16 + grp;
            int o1 = o0 + 8;
            float bias0, slope0, bias1, slope1;
            if (o0 < 128)      { bias0 = b1[o0];       slope0 = a1[0]; }
            else if (o0 < 256) { bias0 = b2[o0 - 128]; slope0 = a2[0]; }
            else               { bias0 = ba[o0 - 256]; slope0 = aa[0]; }
            if (o1 < 128)      { bias1 = b1[o1];       slope1 = a1[0]; }
            else if (o1 < 256) { bias1 = b2[o1 - 128]; slope1 = a2[0]; }
            else               { bias1 = ba[o1 - 256]; slope1 = aa[0]; }
            #pragma unroll
            for (int nj = 0; nj < 4; ++nj) {
                int hw0 = hbase + nh + nj * 8 + 2 * qd;
                float v00 = acc[mi][nj][0] + bias0; v00 = v00 >= 0.f ? v00 : slope0 * v00;
                float v01 = acc[mi][nj][1] + bias0; v01 = v01 >= 0.f ? v01 : slope0 * v01;
                float v10 = acc[mi][nj][2] + bias1; v10 = v10 >= 0.f ? v10 : slope1 * v10;
                float v11 = acc[mi][nj][3] + bias1; v11 = v11 >= 0.f ? v11 : slope1 * v11;
                if (o0 < 128) {
                    gqT[(size_t)hw0 * 128 + o0]       = bf16_bits(v00);
                    gqT[(size_t)(hw0 + 1) * 128 + o0] = bf16_bits(v01);
                    gqT[(size_t)hw0 * 128 + o1]       = bf16_bits(v10);
                    gqT[(size_t)(hw0 + 1) * 128 + o1] = bf16_bits(v11);
                } else if (o0 < 256) {
                    int c0 = o0 - 128, c1 = o1 - 128;
                    gkT[(size_t)hw0 * 128 + c0]       = bf16_bits(v00);
                    gkT[(size_t)(hw0 + 1) * 128 + c0] = bf16_bits(v01);
                    gkT[(size_t)hw0 * 128 + c1]       = bf16_bits(v10);
                    gkT[(size_t)(hw0 + 1) * 128 + c1] = bf16_bits(v11);
                } else {
                    int c0 = o0 - 256, c1 = o1 - 256;
                    *(uint32_t*)(gvb + (size_t)c0 * HW + hw0) = pack_bf16(v00, v01);
                    *(uint32_t*)(gvb + (size_t)c1 * HW + hw0) = pack_bf16(v10, v11);
                }
            }
        }
    }
}

// ---------------------------------------------------------------------------
// Flash attention: BQ=128, BK=64, 1024 threads, bf16 mma.sync.
// SOFTWARE-PIPELINED phases with double-buffered P: QK(kt) -> P[kt&1] while
// PV consumes P[(kt-1)&1] / V[(kt-1)&1]. ONE barrier per k-tile.
// Smem (bytes):
//   Qt [128 q][136 c] bf16 @0          (34,816)
//   K0/K1 [64 j][136 c] bf16 @34,816 / @52,224  (17,408 each)
//   V0/V1 [256 c][72 j] bf16 @69,632 / @106,496 (36,864 each)
//   P0/P1 [128 q][72 k] bf16 @143,360 / @161,792 (18,432 each)
//   redS @180,224 (2,048)  lrow @182,272 (512)  -> total 182,784
// ---------------------------------------------------------------------------
#define OFF_K0 34816
#define OFF_K1 52224
#define OFF_V0 69632
#define OFF_V1 106496
#define OFF_P0 143360
#define OFF_P1 161792
#define OFF_RS 180224
#define OFF_L  182272
#define FL_SMEM 182784

__global__ void __launch_bounds__(1024, 1) flash_kernel(
    const float* __restrict__ x, float* __restrict__ out)
{
    extern __shared__ float sm[];
    float* redS = sm + OFF_RS / 4;
    float* lrow = sm + OFF_L / 4;

    const uint32_t sbase = (uint32_t)__cvta_generic_to_shared(sm);

    const int qtile = blockIdx.x, n = blockIdx.y;
    const int qbase = qtile * 128;
    const int tid  = threadIdx.x;
    const int w    = tid >> 5, lane = tid & 31;
    const int grp  = lane >> 2, qd = lane & 3;

    const uint16_t* QT = g_qT + (size_t)n * HW * 128;
    const uint16_t* KT = g_kT + (size_t)n * HW * 128;
    const uint16_t* VB = g_vb + (size_t)n * 256 * HW;

    // ldmatrix per-thread address parts
    const int rpA = (lane & 7) + (lane & 8);          // A rows (m)
    const int kcA = (lane >> 4) * 16;                 // A k-chunk bytes
    const int rB2 = (lane & 7) + ((lane & 16) >> 1);  // bf16 B rows (n)
    const int cB2 = ((lane >> 3) & 1) * 16;           // bf16 B k-chunk bytes

    // Warp tiling (32 warps)
    const int mq0 = (w & 7) * 16;       // QK: 1 m16 q-tile
    const int kc  = w >> 3;             // QK: 16-key chunk (0..3)
    const int nk0 = kc * 16;
    const int vm0 = (w & 7) * 32;       // PV: 2 m16 c-tiles
    const int qn0 = (w >> 3) * 32;      // PV: 4 n8 q-tiles

    const uint32_t qa_base  = sbase + (uint32_t)((mq0 + rpA) * 272 + kcA);
    const uint32_t kb_base0 = sbase + OFF_K0 + (uint32_t)((nk0 + rB2) * 272 + cB2);
    const uint32_t kb_base1 = sbase + OFF_K1 + (uint32_t)((nk0 + rB2) * 272 + cB2);
    const uint32_t va_base0 = sbase + OFF_V0 + (uint32_t)((vm0 + rpA) * 144 + kcA);
    const uint32_t va_base1 = sbase + OFF_V1 + (uint32_t)((vm0 + rpA) * 144 + kcA);
    const uint32_t pb_base0 = sbase + OFF_P0 + (uint32_t)((qn0 + rB2) * 144 + cB2);
    const uint32_t pb_base1 = sbase + OFF_P1 + (uint32_t)((qn0 + rB2) * 144 + cB2);

    const int r0 = mq0 + grp;           // this thread's softmax rows
    const int r1 = r0 + 8;
    const uint32_t p_off0 = (uint32_t)(r0 * 144 + (nk0 + 2 * qd) * 2);
    const uint32_t p_off1 = (uint32_t)(r1 * 144 + (nk0 + 2 * qd) * 2);

    // Q fill (once) + K(0) prefetch
    {
        int idx = tid;
        #pragma unroll
        for (int r = 0; r < 2; ++r, idx += 1024) {   // Q: 2048 chunks
            int row = idx >> 4, ch = idx & 15;
            cp_async16(sbase + (uint32_t)(row * 272 + ch * 16),
                       QT + (size_t)(qbase + row) * 128 + ch * 8);
        }
        { int j = tid >> 4, ch = tid & 15;           // K(0): 1024 chunks
          cp_async16(sbase + OFF_K0 + (uint32_t)(j * 272 + ch * 16),
                     KT + (size_t)j * 128 + ch * 8); }
        cp_commit();
    }

    float acc[2][4][4] = {};     // O^T fragments [c-tile][q-tile][4]
    float sAcc0 = 0.f, sAcc1 = 0.f;   // register l partials (rows r0, r1)

    for (int kt = 0; kt < HW / 64; ++kt) {
        const int buf = kt & 1;
        cp_wait0();
        __syncthreads();        // single barrier: K(kt), V(kt-1) ready; P/V bufs free

        // ---- prefetch K(kt+1) -> K[buf^1], V(kt) -> V[buf] ----
        {
            if (kt < HW / 64 - 1) {
                const int kb2 = (kt + 1) * 64;
                const uint32_t kdst = sbase + (buf ? OFF_K0 : OFF_K1);
                int j = tid >> 4, ch = tid & 15;
                cp_async16(kdst + (uint32_t)(j * 272 + ch * 16),
                           KT + (size_t)(kb2 + j) * 128 + ch * 8);
            }
            const int vb2 = kt * 64;
            const uint32_t vdst = sbase + (buf ? OFF_V1 : OFF_V0);
            int idx = tid;
            #pragma unroll
            for (int r = 0; r < 2; ++r, idx += 1024) {
                int c = idx >> 3, ch = idx & 7;
                cp_async16(vdst + (uint32_t)(c * 144 + ch * 16),
                           VB + (size_t)c * HW + vb2 + ch * 8);
            }
            cp_commit();
        }

        // ---- S = Q K^T(kt) in registers (K[buf]) ----
        float s[2][4] = {};
        {
            const uint32_t kb = buf ? kb_base1 : kb_base0;
            #pragma unroll
            for (int sp = 0; sp < 8; ++sp) {             // k16 over c=128
                uint32_t a4[4], bq[4];
                ldsm_x4(a4, qa_base + (uint32_t)(sp * 32));
                ldsm_x4(bq, kb + (uint32_t)(sp * 32));
                mma_bf16(s[0], a4, bq[0], bq[1]);
                mma_bf16(s[1], a4, bq[2], bq[3]);
            }
        }

        // ---- unnormalized exp, pack P -> P[buf], accumulate l ----
        {
            const uint32_t pst = sbase + (buf ? OFF_P1 : OFF_P0);
            float p00 = fexp(s[0][0]), p01 = fexp(s[0][1]);
            float p02 = fexp(s[1][0]), p03 = fexp(s[1][1]);
            float p10 = fexp(s[0][2]), p11 = fexp(s[0][3]);
            float p12 = fexp(s[1][2]), p13 = fexp(s[1][3]);
            st_shared_b32(pst + p_off0,      pack_bf16(p00, p01));
            st_shared_b32(pst + p_off0 + 16, pack_bf16(p02, p03));
            st_shared_b32(pst + p_off1,      pack_bf16(p10, p11));
            st_shared_b32(pst + p_off1 + 16, pack_bf16(p12, p13));
            sAcc0 += (p00 + p01) + (p02 + p03);
            sAcc1 += (p10 + p11) + (p12 + p13);
        }

        // ---- PV of PREVIOUS tile: O^T += V(kt-1) P(kt-1)^T ----
        if (kt > 0) {
            const uint32_t va = buf ? va_base0 : va_base1;   // V[buf^1]
            const uint32_t pb = buf ? pb_base0 : pb_base1;   // P[buf^1]
            #pragma unroll
            for (int sp = 0; sp < 4; ++sp) {             // k16 steps over 64 keys
                uint32_t av[2][4];
                ldsm_x4(av[0], va + (uint32_t)(sp * 32));
                ldsm_x4(av[1], va + (uint32_t)(16 * 144 + sp * 32));
                #pragma unroll
                for (int nj = 0; nj < 2; ++nj) {
                    uint32_t bq[4];
                    ldsm_x4(bq, pb + (uint32_t)(nj * 16 * 144 + sp * 32));
                    #pragma unroll
                    for (int mi = 0; mi < 2; ++mi) {
                        mma_bf16(acc[mi][nj * 2],     av[mi], bq[0], bq[1]);
                        mma_bf16(acc[mi][nj * 2 + 1], av[mi], bq[2], bq[3]);
                    }
                }
            }
        }
    }

    // ---- drain: final PV for the last tile ----
    cp_wait0();
    __syncthreads();
    {
        const int lastbuf = (HW / 64 - 1) & 1;               // =1
        const uint32_t va = lastbuf ? va_base1 : va_base0;
        const uint32_t pb = lastbuf ? pb_base1 : pb_base0;
        #pragma unroll
        for (int sp = 0; sp < 4; ++sp) {
            uint32_t av[2][4];
            ldsm_x4(av[0], va + (uint32_t)(sp * 32));
            ldsm_x4(av[1], va + (uint32_t)(16 * 144 + sp * 32));
            #pragma unroll
            for (int nj = 0; nj < 2; ++nj) {
                uint32_t bq[4];
                ldsm_x4(bq, pb + (uint32_t)(nj * 16 * 144 + sp * 32));
                #pragma unroll
                for (int mi = 0; mi < 2; ++mi) {
                    mma_bf16(acc[mi][nj * 2],     av[mi], bq[0], bq[1]);
                    mma_bf16(acc[mi][nj * 2 + 1], av[mi], bq[2], bq[3]);
                }
            }
        }
    }

    // ---- final l reduction: qd-shuffles, cross-warp via redS ----
    sAcc0 += __shfl_xor_sync(0xffffffffu, sAcc0, 1);
    sAcc0 += __shfl_xor_sync(0xffffffffu, sAcc0, 2);
    sAcc1 += __shfl_xor_sync(0xffffffffu, sAcc1, 1);
    sAcc1 += __shfl_xor_sync(0xffffffffu, sAcc1, 2);
    if (qd == 0) {
        redS[kc * 128 + r0] = sAcc0;
        redS[kc * 128 + r1] = sAcc1;
    }
    __syncthreads();
    if (tid < 128)
        lrow[tid] = (redS[tid] + redS[128 + tid]) + (redS[256 + tid] + redS[384 + tid]);
    __syncthreads();

    // ---- epilogue: /l + residual; O^T already [c][hw] ----
    const float* xb = x + (size_t)n * CH * HW;
    float* ob = out + (size_t)n * CH * HW;
    #pragma unroll
    for (int ni = 0; ni < 4; ++ni) {
        int q0 = qn0 + ni * 8 + 2 * qd;
        float inv0 = 1.f / lrow[q0];
        float inv1 = 1.f / lrow[q0 + 1];
        #pragma unroll
        for (int mi = 0; mi < 2; ++mi) {
            int c0 = vm0 + mi * 16 + grp;
            size_t g0 = (size_t)c0 * HW + qbase + q0;
            size_t g1 = (size_t)(c0 + 8) * HW + qbase + q0;
            float2 x0 = *(const float2*)(xb + g0);
            float2 x1 = *(const float2*)(xb + g1);
            *(float2*)(ob + g0) = make_float2(acc[mi][ni][0] * inv0 + x0.x,
                                              acc[mi][ni][1] * inv1 + x0.y);
            *(float2*)(ob + g1) = make_float2(acc[mi][ni][2] * inv0 + x1.x,
                                              acc[mi][ni][3] * inv1 + x1.y);
        }
    }
}

// ---------------------------------------------------------------------------
extern "C" void kernel_launch(void* const* d_in, const int* in_sizes, int n_in,
                              void* d_out, int out_size)
{
    const float* x  = (const float*)d_in[0];
    const float* w1 = (const float*)d_in[1];
    const float* b1 = (const float*)d_in[2];
    const float* a1 = (const float*)d_in[3];
    const float* w2 = (const float*)d_in[4];
    const float* b2 = (const float*)d_in[5];
    const float* a2 = (const float*)d_in[6];
    const float* wa = (const float*)d_in[7];
    const float* ba = (const float*)d_in[8];
    const float* aa = (const float*)d_in[9];
    float* out = (float*)d_out;

    cudaFuncSetAttribute(stage1_kernel, cudaFuncAttributeMaxDynamicSharedMemorySize, S1_SMEM);
    cudaFuncSetAttribute(flash_kernel,  cudaFuncAttributeMaxDynamicSharedMemorySize, FL_SMEM);

    stage1_kernel<<<dim3(HW / 128, NB), 256, S1_SMEM>>>(x, w1, b1, a1, w2, b2, a2, wa, ba, aa);
    flash_kernel<<<dim3(HW / 128, NB), 1024, FL_SMEM>>>(x, out);
}

// round 15
// speedup vs baseline: 1.1476x; 1.1476x over previous
#include <cuda_runtime.h>
#include <math.h>
#include <stdint.h>

#define HW  4096
#define CH  256
#define NB  4

// Stage-1 outputs (all bf16)
__device__ uint16_t g_qT[(size_t)NB * HW * 128];   // q: [n][hw][c]
__device__ uint16_t g_kT[(size_t)NB * HW * 128];   // k: [n][hw][c]
__device__ uint16_t g_vb[(size_t)NB * 256 * HW];   // v: [n][c][hw]

// ---------------------------------------------------------------------------
__device__ __forceinline__ uint32_t pack_bf16(float lo, float hi) {
    uint32_t r;
    asm("cvt.rn.bf16x2.f32 %0, %1, %2;" : "=r"(r) : "f"(hi), "f"(lo));
    return r;
}
__device__ __forceinline__ uint16_t bf16_bits(float x) {
    uint16_t r;
    asm("cvt.rn.bf16.f32 %0, %1;" : "=h"(r) : "f"(x));
    return r;
}

__device__ __forceinline__ void mma_u(float* d, const uint32_t* a, uint32_t b0, uint32_t b1) {
    asm volatile(
        "mma.sync.aligned.m16n8k8.row.col.f32.tf32.tf32.f32 "
        "{%0,%1,%2,%3},{%4,%5,%6,%7},{%8,%9},{%0,%1,%2,%3};\n"
        : "+f"(d[0]), "+f"(d[1]), "+f"(d[2]), "+f"(d[3])
        : "r"(a[0]), "r"(a[1]), "r"(a[2]), "r"(a[3]), "r"(b0), "r"(b1));
}

__device__ __forceinline__ void mma_bf16(float* d, const uint32_t* a, uint32_t b0, uint32_t b1) {
    asm volatile(
        "mma.sync.aligned.m16n8k16.row.col.f32.bf16.bf16.f32 "
        "{%0,%1,%2,%3},{%4,%5,%6,%7},{%8,%9},{%0,%1,%2,%3};\n"
        : "+f"(d[0]), "+f"(d[1]), "+f"(d[2]), "+f"(d[3])
        : "r"(a[0]), "r"(a[1]), "r"(a[2]), "r"(a[3]), "r"(b0), "r"(b1));
}

__device__ __forceinline__ void ldsm_x4(uint32_t* r, uint32_t saddr) {
    asm volatile("ldmatrix.sync.aligned.m8n8.x4.shared.b16 {%0,%1,%2,%3}, [%4];"
                 : "=r"(r[0]), "=r"(r[1]), "=r"(r[2]), "=r"(r[3]) : "r"(saddr));
}

__device__ __forceinline__ void st_shared_b32(uint32_t saddr, uint32_t v) {
    asm volatile("st.shared.b32 [%0], %1;" :: "r"(saddr), "r"(v));
}

__device__ __forceinline__ void cp_async16(uint32_t saddr, const void* gptr) {
    asm volatile("cp.async.ca.shared.global [%0], [%1], 16;\n" :: "r"(saddr), "l"(gptr));
}
__device__ __forceinline__ void cp_commit() {
    asm volatile("cp.async.commit_group;\n" ::: "memory");
}
__device__ __forceinline__ void cp_wait0() {
    asm volatile("cp.async.wait_group 0;\n" ::: "memory");
}

// Fast e^x on the FMA pipe
__device__ __forceinline__ float fexp(float x) {
    float y = fmaxf(x * 1.4426950408889634f, -126.0f);
    float n = rintf(y);
    float f = y - n;
    float p = 1.3333558e-3f;
    p = p * f + 9.6181291e-3f;
    p = p * f + 5.5504109e-2f;
    p = p * f + 2.4022650e-1f;
    p = p * f + 6.9314718e-1f;
    p = p * f + 1.0f;
    return p * __int_as_float(((int)n + 127) << 23);
}

// ---------------------------------------------------------------------------
// Stage 1: x-resident, ldsm + tf32 mma, W fills via cp.async. (unchanged)
// ---------------------------------------------------------------------------
#define S1_ST 260
#define S1_OFF_W (128 * S1_ST)
#define S1_SMEM ((128 + 64) * S1_ST * 4)

__global__ void __launch_bounds__(256) stage1_kernel(
    const float* __restrict__ x,
    const float* __restrict__ w1, const float* __restrict__ b1, const float* __restrict__ a1,
    const float* __restrict__ w2, const float* __restrict__ b2, const float* __restrict__ a2,
    const float* __restrict__ wa, const float* __restrict__ ba, const float* __restrict__ aa)
{
    extern __shared__ float sm[];
    float* XsT = sm;
    const uint32_t sbase = (uint32_t)__cvta_generic_to_shared(sm);

    const int hbase = blockIdx.x * 128;
    const int n     = blockIdx.y;
    const int tid   = threadIdx.x;
    const int w = tid >> 5, lane = tid & 31, grp = lane >> 2, qd = lane & 3;

    const float* xb = x + (size_t)n * CH * HW;

    for (int idx = tid; idx < 256 * 128; idx += 256) {
        int c = idx >> 7, hh = idx & 127;
        XsT[hh * S1_ST + c] = xb[(size_t)c * HW + hbase + hh];
    }

    const int rpA = (lane & 7) + (lane & 8);
    const int kcA = (lane >> 4) * 16;
    const int rpB = lane & 7;
    const int cbB = (lane >> 3) * 16;

    const int mo = (w & 1) * 32;
    const int nh = (w >> 1) * 32;

    const uint32_t wa_base = sbase + (uint32_t)((S1_OFF_W + (mo + rpA) * S1_ST) * 4 + kcA);
    const uint32_t xb_base = sbase + (uint32_t)(((nh + rpB) * S1_ST) * 4 + cbB);

    uint16_t* gqT = g_qT + (size_t)n * HW * 128;
    uint16_t* gkT = g_kT + (size_t)n * HW * 128;
    uint16_t* gvb = g_vb + (size_t)n * 256 * HW;

    for (int ob = 0; ob < 8; ++ob) {
        const int obase = ob * 64;
        __syncthreads();
        #pragma unroll 4
        for (int r = 0; r < 16; ++r) {
            int idx = tid + r * 256;
            int oo = idx >> 6, ch = idx & 63;
            int o = obase + oo;
            const float* wp = (o < 128) ? w1 + (size_t)o * CH
                            : (o < 256) ? w2 + (size_t)(o - 128) * CH
                                        : wa + (size_t)(o - 256) * CH;
            cp_async16(sbase + (uint32_t)((S1_OFF_W + oo * S1_ST) * 4 + ch * 16),
                       wp + ch * 4);
        }
        cp_commit(); cp_wait0();
        __syncthreads();

        float acc[2][4][4] = {};
        #pragma unroll 4
        for (int sp = 0; sp < 16; ++sp) {
            uint32_t av[2][2][4];
            #pragma unroll
            for (int mi = 0; mi < 2; ++mi) {
                ldsm_x4(av[mi][0], wa_base + (uint32_t)(mi * 16 * S1_ST * 4 + sp * 64));
                ldsm_x4(av[mi][1], wa_base + (uint32_t)(mi * 16 * S1_ST * 4 + sp * 64 + 32));
            }
            #pragma unroll
            for (int nj = 0; nj < 4; ++nj) {
                uint32_t bq[4];
                ldsm_x4(bq, xb_base + (uint32_t)(nj * 8 * S1_ST * 4 + sp * 64));
                #pragma unroll
                for (int mi = 0; mi < 2; ++mi) {
                    mma_u(acc[mi][nj], av[mi][0], bq[0], bq[1]);
                    mma_u(acc[mi][nj], av[mi][1], bq[2], bq[3]);
                }
            }
        }

        #pragma unroll
        for (int mi = 0; mi < 2; ++mi) {
            int o0 = obase + mo + mi * 16 + grp;
            int o1 = o0 + 8;
            float bias0, slope0, bias1, slope1;
            if (o0 < 128)      { bias0 = b1[o0];       slope0 = a1[0]; }
            else if (o0 < 256) { bias0 = b2[o0 - 128]; slope0 = a2[0]; }
            else               { bias0 = ba[o0 - 256]; slope0 = aa[0]; }
            if (o1 < 128)      { bias1 = b1[o1];       slope1 = a1[0]; }
            else if (o1 < 256) { bias1 = b2[o1 - 128]; slope1 = a2[0]; }
            else               { bias1 = ba[o1 - 256]; slope1 = aa[0]; }
            #pragma unroll
            for (int nj = 0; nj < 4; ++nj) {
                int hw0 = hbase + nh + nj * 8 + 2 * qd;
                float v00 = acc[mi][nj][0] + bias0; v00 = v00 >= 0.f ? v00 : slope0 * v00;
                float v01 = acc[mi][nj][1] + bias0; v01 = v01 >= 0.f ? v01 : slope0 * v01;
                float v10 = acc[mi][nj][2] + bias1; v10 = v10 >= 0.f ? v10 : slope1 * v10;
                float v11 = acc[mi][nj][3] + bias1; v11 = v11 >= 0.f ? v11 : slope1 * v11;
                if (o0 < 128) {
                    gqT[(size_t)hw0 * 128 + o0]       = bf16_bits(v00);
                    gqT[(size_t)(hw0 + 1) * 128 + o0] = bf16_bits(v01);
                    gqT[(size_t)hw0 * 128 + o1]       = bf16_bits(v10);
                    gqT[(size_t)(hw0 + 1) * 128 + o1] = bf16_bits(v11);
                } else if (o0 < 256) {
                    int c0 = o0 - 128, c1 = o1 - 128;
                    gkT[(size_t)hw0 * 128 + c0]       = bf16_bits(v00);
                    gkT[(size_t)(hw0 + 1) * 128 + c0] = bf16_bits(v01);
                    gkT[(size_t)hw0 * 128 + c1]       = bf16_bits(v10);
                    gkT[(size_t)(hw0 + 1) * 128 + c1] = bf16_bits(v11);
                } else {
                    int c0 = o0 - 256, c1 = o1 - 256;
                    *(uint32_t*)(gvb + (size_t)c0 * HW + hw0) = pack_bf16(v00, v01);
                    *(uint32_t*)(gvb + (size_t)c1 * HW + hw0) = pack_bf16(v10, v11);
                }
            }
        }
    }
}

// ---------------------------------------------------------------------------
// Flash attention: BQ=128, BK=64, 512 threads (16 warps), bf16 mma.sync.
// Q REGISTER-RESIDENT (32 regs/thread, loaded once). No Q smem tile.
// Unnormalized softmax, register l accumulators, 2 barriers/iter (R13 sched).
// Per-warp tiles: QK 16q x 32k; PV 32c x 64q (acc = 64 regs).
// Smem (bytes):
//   K0/K1 [64 j][136 c] bf16 @0 / @17,408       (17,408 each)
//   V0/V1 [256 c][72 j] bf16 @34,816 / @71,680  (36,864 each)
//   P  [128 q][72 k] bf16 @108,544              (18,432)
//   redS @126,976 (1,024)  lrow @128,000 (512)  -> total 128,512
// ---------------------------------------------------------------------------
#define OFF_K0 0
#define OFF_K1 17408
#define OFF_V0 34816
#define OFF_V1 71680
#define OFF_P  108544
#define OFF_RS 126976
#define OFF_L  128000
#define FL_SMEM 128512

__global__ void __launch_bounds__(512, 1) flash_kernel(
    const float* __restrict__ x, float* __restrict__ out)
{
    extern __shared__ float sm[];
    float* redS = sm + OFF_RS / 4;
    float* lrow = sm + OFF_L / 4;

    const uint32_t sbase = (uint32_t)__cvta_generic_to_shared(sm);

    const int qtile = blockIdx.x, n = blockIdx.y;
    const int qbase = qtile * 128;
    const int tid  = threadIdx.x;
    const int w    = tid >> 5, lane = tid & 31;
    const int grp  = lane >> 2, qd = lane & 3;

    const uint16_t* QT = g_qT + (size_t)n * HW * 128;
    const uint16_t* KT = g_kT + (size_t)n * HW * 128;
    const uint16_t* VB = g_vb + (size_t)n * 256 * HW;

    // ldmatrix per-thread address parts
    const int rpA = (lane & 7) + (lane & 8);          // A rows (m)
    const int kcA = (lane >> 4) * 16;                 // A k-chunk bytes
    const int rB2 = (lane & 7) + ((lane & 16) >> 1);  // bf16 B rows (n)
    const int cB2 = ((lane >> 3) & 1) * 16;           // bf16 B k-chunk bytes

    // Warp tiling (16 warps)
    const int mq0 = (w & 7) * 16;       // QK: 1 m16 q-tile
    const int kc2 = w >> 3;             // QK: 32-key half (0..1)
    const int nk0 = kc2 * 32;
    const int vm0 = (w & 7) * 32;       // PV: 2 m16 c-tiles
    const int qn0 = (w >> 3) * 64;      // PV: 8 n8 q-tiles

    const uint32_t kb_base0 = sbase + OFF_K0 + (uint32_t)((nk0 + rB2) * 272 + cB2);
    const uint32_t kb_base1 = sbase + OFF_K1 + (uint32_t)((nk0 + rB2) * 272 + cB2);
    const uint32_t va_base0 = sbase + OFF_V0 + (uint32_t)((vm0 + rpA) * 144 + kcA);
    const uint32_t va_base1 = sbase + OFF_V1 + (uint32_t)((vm0 + rpA) * 144 + kcA);
    const uint32_t pb_base  = sbase + OFF_P + (uint32_t)((qn0 + rB2) * 144 + cB2);

    const int r0 = mq0 + grp;           // this thread's softmax rows
    const int r1 = r0 + 8;
    const uint32_t p_st0 = sbase + OFF_P + (uint32_t)(r0 * 144 + (nk0 + 2 * qd) * 2);
    const uint32_t p_st1 = sbase + OFF_P + (uint32_t)(r1 * 144 + (nk0 + 2 * qd) * 2);

    // ---- Q A-fragments: loaded ONCE from global, resident all 64 iters ----
    uint32_t qA[8][4];
    {
        const uint16_t* qrow = QT + (size_t)(qbase + mq0 + grp) * 128 + 2 * qd;
        #pragma unroll
        for (int sp = 0; sp < 8; ++sp) {
            const uint16_t* b = qrow + sp * 16;
            qA[sp][0] = *(const uint32_t*)b;                // (grp,   k 0-7)
            qA[sp][1] = *(const uint32_t*)(b + 8 * 128);    // (grp+8, k 0-7)
            qA[sp][2] = *(const uint32_t*)(b + 8);          // (grp,   k 8-15)
            qA[sp][3] = *(const uint32_t*)(b + 8 * 128 + 8);// (grp+8, k 8-15)
        }
    }

    // First K(0)/V(0) fill
    {
        int idx = tid;
        #pragma unroll
        for (int r = 0; r < 2; ++r, idx += 512) {    // K: 1024 chunks
            int j = idx >> 4, ch = idx & 15;
            cp_async16(sbase + OFF_K0 + (uint32_t)(j * 272 + ch * 16),
                       KT + (size_t)j * 128 + ch * 8);
        }
        idx = tid;
        #pragma unroll
        for (int r = 0; r < 4; ++r, idx += 512) {    // V: 2048 chunks
            int c = idx >> 3, ch = idx & 7;
            cp_async16(sbase + OFF_V0 + (uint32_t)(c * 144 + ch * 16),
                       VB + (size_t)c * HW + ch * 8);
        }
        cp_commit();
    }

    float acc[2][8][4] = {};     // O^T fragments [c-tile][q-tile][4]
    float sAcc0 = 0.f, sAcc1 = 0.f;

    for (int kt = 0; kt < HW / 64; ++kt) {
        const int buf = kt & 1;
        cp_wait0();
        __syncthreads();                                 // sync1: K/V(kt) ready, prior PV done

        // ---- prefetch kt+1 K/V into the other buffer ----
        if (kt < HW / 64 - 1) {
            const int kb2 = (kt + 1) * 64;
            const uint32_t kdst = sbase + (buf ? OFF_K0 : OFF_K1);
            const uint32_t vdst = sbase + (buf ? OFF_V0 : OFF_V1);
            int idx = tid;
            #pragma unroll
            for (int r = 0; r < 2; ++r, idx += 512) {
                int j = idx >> 4, ch = idx & 15;
                cp_async16(kdst + (uint32_t)(j * 272 + ch * 16),
                           KT + (size_t)(kb2 + j) * 128 + ch * 8);
            }
            idx = tid;
            #pragma unroll
            for (int r = 0; r < 4; ++r, idx += 512) {
                int c = idx >> 3, ch = idx & 7;
                cp_async16(vdst + (uint32_t)(c * 144 + ch * 16),
                           VB + (size_t)c * HW + kb2 + ch * 8);
            }
            cp_commit();
        }

        // ---- S = Q K^T : 16q x 32k per warp, Q from registers ----
        float s[4][4] = {};
        {
            const uint32_t kb = buf ? kb_base1 : kb_base0;
            #pragma unroll
            for (int sp = 0; sp < 8; ++sp) {             // k16 over c=128
                uint32_t bqa[4], bqb[4];
                ldsm_x4(bqa, kb + (uint32_t)(sp * 32));
                ldsm_x4(bqb, kb + (uint32_t)(16 * 272 + sp * 32));
                mma_bf16(s[0], qA[sp], bqa[0], bqa[1]);
                mma_bf16(s[1], qA[sp], bqa[2], bqa[3]);
                mma_bf16(s[2], qA[sp], bqb[0], bqb[1]);
                mma_bf16(s[3], qA[sp], bqb[2], bqb[3]);
            }
        }

        // ---- unnormalized exp, pack P, accumulate l in registers ----
        {
            #pragma unroll
            for (int j = 0; j < 4; ++j) {
                float p0 = fexp(s[j][0]), p1 = fexp(s[j][1]);
                float p2 = fexp(s[j][2]), p3 = fexp(s[j][3]);
                st_shared_b32(p_st0 + j * 16, pack_bf16(p0, p1));
                st_shared_b32(p_st1 + j * 16, pack_bf16(p2, p3));
                sAcc0 += p0 + p1;
                sAcc1 += p2 + p3;
            }
        }
        __syncthreads();                                 // sync2: P ready

        // ---- O^T += V P^T : 32c x 64q per warp ----
        {
            const uint32_t va = buf ? va_base1 : va_base0;
            #pragma unroll
            for (int sp = 0; sp < 4; ++sp) {             // k16 steps over 64 keys
                uint32_t av[2][4];
                ldsm_x4(av[0], va + (uint32_t)(sp * 32));
                ldsm_x4(av[1], va + (uint32_t)(16 * 144 + sp * 32));
                #pragma unroll
                for (int g = 0; g < 4; ++g) {            // n16 groups over 64 q
                    uint32_t bq[4];
                    ldsm_x4(bq, pb_base + (uint32_t)(g * 16 * 144 + sp * 32));
                    #pragma unroll
                    for (int mi = 0; mi < 2; ++mi) {
                        mma_bf16(acc[mi][g * 2],     av[mi], bq[0], bq[1]);
                        mma_bf16(acc[mi][g * 2 + 1], av[mi], bq[2], bq[3]);
                    }
                }
            }
        }
    }

    // ---- final l reduction: qd-shuffles, cross-warp via redS ----
    sAcc0 += __shfl_xor_sync(0xffffffffu, sAcc0, 1);
    sAcc0 += __shfl_xor_sync(0xffffffffu, sAcc0, 2);
    sAcc1 += __shfl_xor_sync(0xffffffffu, sAcc1, 1);
    sAcc1 += __shfl_xor_sync(0xffffffffu, sAcc1, 2);
    if (qd == 0) {
        redS[kc2 * 128 + r0] = sAcc0;
        redS[kc2 * 128 + r1] = sAcc1;
    }
    __syncthreads();
    if (tid < 128)
        lrow[tid] = redS[tid] + redS[128 + tid];
    __syncthreads();

    // ---- epilogue: /l + residual; O^T already [c][hw] ----
    const float* xb = x + (size_t)n * CH * HW;
    float* ob = out + (size_t)n * CH * HW;
    #pragma unroll
    for (int ni = 0; ni < 8; ++ni) {
        int q0 = qn0 + ni * 8 + 2 * qd;
        float inv0 = 1.f / lrow[q0];
        float inv1 = 1.f / lrow[q0 + 1];
        #pragma unroll
        for (int mi = 0; mi < 2; ++mi) {
            int c0 = vm0 + mi * 16 + grp;
            size_t g0 = (size_t)c0 * HW + qbase + q0;
            size_t g1 = (size_t)(c0 + 8) * HW + qbase + q0;
            float2 x0 = *(const float2*)(xb + g0);
            float2 x1 = *(const float2*)(xb + g1);
            *(float2*)(ob + g0) = make_float2(acc[mi][ni][0] * inv0 + x0.x,
                                              acc[mi][ni][1] * inv1 + x0.y);
            *(float2*)(ob + g1) = make_float2(acc[mi][ni][2] * inv0 + x1.x,
                                              acc[mi][ni][3] * inv1 + x1.y);
        }
    }
}

// ---------------------------------------------------------------------------
extern "C" void kernel_launch(void* const* d_in, const int* in_sizes, int n_in,
                              void* d_out, int out_size)
{
    const float* x  = (const float*)d_in[0];
    const float* w1 = (const float*)d_in[1];
    const float* b1 = (const float*)d_in[2];
    const float* a1 = (const float*)d_in[3];
    const float* w2 = (const float*)d_in[4];
    const float* b2 = (const float*)d_in[5];
    const float* a2 = (const float*)d_in[6];
    const float* wa = (const float*)d_in[7];
    const float* ba = (const float*)d_in[8];
    const float* aa = (const float*)d_in[9];
    float* out = (float*)d_out;

    cudaFuncSetAttribute(stage1_kernel, cudaFuncAttributeMaxDynamicSharedMemorySize, S1_SMEM);
    cudaFuncSetAttribute(flash_kernel,  cudaFuncAttributeMaxDynamicSharedMemorySize, FL_SMEM);

    stage1_kernel<<<dim3(HW / 128, NB), 256, S1_SMEM>>>(x, w1, b1, a1, w2, b2, a2, wa, ba, aa);
    flash_kernel<<<dim3(HW / 128, NB), 512, FL_SMEM>>>(x, out);
}